// round 17
// baseline (speedup 1.0000x reference)
#include <cuda_runtime.h>

// FINAL (R11): out[m][n] = C[m][n] * D[n];  8192 x 8192 f32, row-major.
// Best measured: 81.9-82.0 us harness / 74.0-75.7 us kernel, ~6.5 TB/s
// (82% of 8 TB/s spec) across 4 independent runs.
//
// Structure: single pass, 16384 blocks x 256 threads x 4 float4. The 4
// per-thread accesses are spaced STRIDE = 64 MB apart, spreading concurrent
// requests across all HBM channels / both L2 dies. STRIDE % NR4 == 0, so each
// thread's column index is invariant -> D loaded exactly once per thread.
// Write-through stores (__stwt): the only store policy that never measured
// worse than default.
//
// Session conclusion (14 measured variants): occupancy 47-84%, MLP 4-8,
// 128/256-bit accesses, batch 4/8, block 256/512, persistent grid, three
// stride layouts, all cache policies — every variant lands at 6.3-6.6 TB/s.
// The kernel is pinned at the mixed read+write HBM controller ceiling with
// compute and issue fully slack; the 512 MB traffic floor is irreducible.
// TMA/smem staging ruled out: LTS throughput is path-independent on B300.

static constexpr int NR4    = 2048;                 // float4s per row
static constexpr int STRIDE = 16384 * 256;          // grid * block = 4,194,304

__global__ __launch_bounds__(256, 6)
void colscale_kernel(const float4* __restrict__ C,
                     const float4* __restrict__ D,
                     float4* __restrict__ out)
{
    const int i = blockIdx.x * 256 + threadIdx.x;   // 0 .. 4,194,303

    // STRIDE is a multiple of NR4, so column index is invariant across the 4.
    const float4 d = __ldg(&D[i & (NR4 - 1)]);

    const int i0 = i;
    const int i1 = i + STRIDE;
    const int i2 = i + 2 * STRIDE;
    const int i3 = i + 3 * STRIDE;

    // Front-batched loads (MLP=4), 64 MB apart.
    float4 c0 = C[i0];
    float4 c1 = C[i1];
    float4 c2 = C[i2];
    float4 c3 = C[i3];

    c0.x *= d.x; c0.y *= d.y; c0.z *= d.z; c0.w *= d.w;
    c1.x *= d.x; c1.y *= d.y; c1.z *= d.z; c1.w *= d.w;
    c2.x *= d.x; c2.y *= d.y; c2.z *= d.z; c2.w *= d.w;
    c3.x *= d.x; c3.y *= d.y; c3.z *= d.z; c3.w *= d.w;

    __stwt(&out[i0], c0);
    __stwt(&out[i1], c1);
    __stwt(&out[i2], c2);
    __stwt(&out[i3], c3);
}

extern "C" void kernel_launch(void* const* d_in, const int* in_sizes, int n_in,
                              void* d_out, int out_size)
{
    const float4* C = (const float4*)d_in[0];
    const float4* D = (const float4*)d_in[1];
    float4* out     = (float4*)d_out;

    colscale_kernel<<<16384, 256>>>(C, D, out);
}